// round 15
// baseline (speedup 1.0000x reference)
#include <cuda_runtime.h>
#include <math.h>

#define LSEQ 128
#define BB   4
#define DD   768
#define HH   300
#define G5   1500
#define K3   900
#define NTAG 7
#define NREL 12
#define NBLK 64

// ---------------- persistent recurrence state ----------------
struct RecurState {
    unsigned bar;
    unsigned pad[31];
    float h[BB * HH];
    float c[2][BB * HH];
    float gates[BB * G5];
};
__device__ RecurState g_rs;

// ---------------- scratch (device globals; no allocs) ----------------
__device__ float d_pre [LSEQ * BB * G5];
__device__ float d_hner[LSEQ * BB * HH];
__device__ float d_hre [LSEQ * BB * HH];
__device__ float d_hsh [LSEQ * BB * HH];
__device__ float d_glob[LSEQ * BB * HH];
__device__ float d_gmax[BB * HH];
__device__ float d_Pst [LSEQ * BB * HH];
__device__ float d_Pen [LSEQ * BB * HH];
__device__ float d_Pg  [BB * HH];

// ---------------- warp helpers ----------------
__device__ __forceinline__ float wsum(float v) {
#pragma unroll
    for (int o = 16; o; o >>= 1) v += __shfl_xor_sync(0xffffffffu, v, o);
    return v;
}
__device__ __forceinline__ float wmax(float v) {
#pragma unroll
    for (int o = 16; o; o >>= 1) v = fmaxf(v, __shfl_xor_sync(0xffffffffu, v, o));
    return v;
}

// software grid barrier (all NBLK CTAs co-resident; counter memset to 0 per launch)
__device__ __forceinline__ void gbar(unsigned target) {
    __syncthreads();
    if (threadIdx.x == 0) {
        __threadfence();
        atomicAdd(&g_rs.bar, 1u);
        unsigned v;
        do {
            asm volatile("ld.acquire.gpu.global.b32 %0, [%1];"
                         : "=r"(v) : "l"(&g_rs.bar) : "memory");
        } while (v < target);
    }
    __syncthreads();
}

// ---------------- persistent recurrence kernel ----------------
__global__ __launch_bounds__(256) void recur_kernel(
    const float* __restrict__ W_hh, const float* __restrict__ b_hh,
    const float* __restrict__ W_tr, const float* __restrict__ b_tr)
{
    __shared__ float sh[BB * HH];        // h carry
    __shared__ float sscan[16][HH];      // 4 cummax curves x 4 batches
    __shared__ float scat[BB][3 * HH];   // [c_re | c_ner | share]

    const int tid  = threadIdx.x;
    const int bid  = blockIdx.x;
    const int warp = tid >> 5;
    const int lane = tid & 31;
    unsigned target = 0;

    for (int l = 0; l < LSEQ; l++) {
        // ---- Phase A: gates = pre[l] + h @ W_hh^T + b_hh ----
        for (int i = tid; i < BB * HH; i += 256) sh[i] = __ldcg(&g_rs.h[i]);
        __syncthreads();

        const int g0 = bid * 24 + warp * 3;
#pragma unroll
        for (int gi = 0; gi < 3; gi++) {
            int g = g0 + gi;
            if (g < G5) {
                float p0 = 0.f, p1 = 0.f, p2 = 0.f, p3 = 0.f;
                for (int k = lane; k < HH; k += 32) {
                    float w = W_hh[g * HH + k];
                    p0 = fmaf(w, sh[0 * HH + k], p0);
                    p1 = fmaf(w, sh[1 * HH + k], p1);
                    p2 = fmaf(w, sh[2 * HH + k], p2);
                    p3 = fmaf(w, sh[3 * HH + k], p3);
                }
                p0 = wsum(p0); p1 = wsum(p1); p2 = wsum(p2); p3 = wsum(p3);
                if (lane == 0) {
                    float bb = b_hh[g];
                    __stcg(&g_rs.gates[0 * G5 + g], d_pre[(l * BB + 0) * G5 + g] + bb + p0);
                    __stcg(&g_rs.gates[1 * G5 + g], d_pre[(l * BB + 1) * G5 + g] + bb + p1);
                    __stcg(&g_rs.gates[2 * G5 + g], d_pre[(l * BB + 2) * G5 + g] + bb + p2);
                    __stcg(&g_rs.gates[3 * G5 + g], d_pre[(l * BB + 3) * G5 + g] + bb + p3);
                }
            }
        }
        target += NBLK; gbar(target);

        // ---- Phase C1: cummax scans (redundant per block; warp-level) ----
        for (int sc = warp; sc < 16; sc += 8) {
            int b  = sc >> 2;
            int ch = (sc & 3) + 1;              // raw chunks 1..4
            const float* row = &g_rs.gates[b * G5 + ch * HH];
            float v[10];
            float mx = -INFINITY;
            if (lane < 30) {
#pragma unroll
                for (int t = 0; t < 10; t++) { v[t] = __ldcg(&row[lane * 10 + t]); mx = fmaxf(mx, v[t]); }
            }
            mx = wmax(mx);
            float loc = 0.f;
            if (lane < 30) {
#pragma unroll
                for (int t = 0; t < 10; t++) { float e = expf(v[t] - mx); loc += e; v[t] = loc; }
            }
            float run = loc;
#pragma unroll
            for (int o = 1; o < 32; o <<= 1) {
                float x = __shfl_up_sync(0xffffffffu, run, o);
                if (lane >= o) run += x;
            }
            float total = __shfl_sync(0xffffffffu, run, 31);
            float off = run - loc;
            float inv = 1.0f / total;
            bool isEg = ((sc & 3) == 0) || ((sc & 3) == 2);   // eg_cin, eg_c -> 1 - cummax
            if (lane < 30) {
#pragma unroll
                for (int t = 0; t < 10; t++) {
                    float cm = (off + v[t]) * inv;
                    sscan[sc][lane * 10 + t] = isEg ? (1.0f - cm) : cm;
                }
            }
        }
        __syncthreads();

        // ---- Phase C2: combine (elementwise) ----
        const int rd = l & 1, wr = (l & 1) ^ 1;
        for (int idx = tid; idx < BB * HH; idx += 256) {
            int b = idx / HH, hh = idx % HH;
            float c   = tanhf(__ldcg(&g_rs.gates[b * G5 + hh]));
            float cin = __ldcg(&g_rs.c[rd][idx]);
            float egi = sscan[b * 4 + 0][hh];
            float rgi = sscan[b * 4 + 1][hh];
            float egc = sscan[b * 4 + 2][hh];
            float rgc = sscan[b * 4 + 3][hh];
            float ovc = rgc * egc, upc = rgc - ovc, dnc = egc - ovc;
            float ovi = rgi * egi, upi = rgi - ovi, dni = egi - ovi;
            float share = ovi * cin + ovc * c;
            float cre   = upi * cin + upc * c + share;
            float cner  = dni * cin + dnc * c + share;
            scat[b][hh]          = cre;
            scat[b][HH + hh]     = cner;
            scat[b][2 * HH + hh] = share;
            if (bid == b) {
                d_hre [(l * BB + b) * HH + hh] = tanhf(cre);
                d_hner[(l * BB + b) * HH + hh] = tanhf(cner);
                d_hsh [(l * BB + b) * HH + hh] = tanhf(share);
            }
        }
        __syncthreads();

        // ---- Phase C3: c_out = cat @ W_tr^T + b_tr ; h = tanh(c_out) ----
        const int o0 = bid * 5;
        for (int oi = warp; oi < 20; oi += 8) {
            int b = oi / 5;
            int o = o0 + (oi % 5);
            if (o < HH) {
                float acc = 0.f;
                for (int k = lane; k < 3 * HH; k += 32)
                    acc = fmaf(scat[b][k], W_tr[o * K3 + k], acc);
                acc = wsum(acc);
                if (lane == 0) {
                    float co = acc + b_tr[o];
                    __stcg(&g_rs.c[wr][b * HH + o], co);
                    __stcg(&g_rs.h[b * HH + o], tanhf(co));
                }
            }
        }
        target += NBLK; gbar(target);
    }
}

// ---------------- generic tiled GEMM: C[m,n] = act( sum A1*W[:,kw1..] + sum A2*W[:,kw2..] + bias ) ----------------
#define TBM 64
#define TBN 64
#define TBK 16
__global__ __launch_bounds__(256) void gemm_rt(
    const float* __restrict__ A1, int lda1,
    const float* __restrict__ A2, int lda2,
    const float* __restrict__ W, int ldw, int kw1, int kw2,
    const float* __restrict__ bias,
    float* __restrict__ C, int ldc,
    int M, int N, int K1, int K2, int act)
{
    __shared__ float sA[TBK][TBM + 1];
    __shared__ float sW[TBK][TBN + 1];
    const int tid = threadIdx.x;
    const int tx = tid & 15, ty = tid >> 4;
    const int bn = blockIdx.x * TBN, bm = blockIdx.y * TBM;
    float acc[4][4] = {};

    for (int pass = 0; pass < 2; pass++) {
        const float* A = pass ? A2 : A1;
        const int K   = pass ? K2 : K1;
        const int lda = pass ? lda2 : lda1;
        const int kw  = pass ? kw2 : kw1;
        if (A == nullptr || K <= 0) continue;
        for (int k0 = 0; k0 < K; k0 += TBK) {
            for (int i = tid; i < TBM * TBK; i += 256) {
                int r = i >> 4, kk = i & 15;
                int gm = bm + r, gk = k0 + kk;
                sA[kk][r] = (gm < M && gk < K) ? A[gm * lda + gk] : 0.0f;
            }
            for (int i = tid; i < TBN * TBK; i += 256) {
                int r = i >> 4, kk = i & 15;
                int gn = bn + r, gk = k0 + kk;
                sW[kk][r] = (gn < N && gk < K) ? W[gn * ldw + kw + gk] : 0.0f;
            }
            __syncthreads();
#pragma unroll
            for (int kk = 0; kk < TBK; kk++) {
                float a[4], w[4];
#pragma unroll
                for (int i = 0; i < 4; i++) a[i] = sA[kk][ty * 4 + i];
#pragma unroll
                for (int j = 0; j < 4; j++) w[j] = sW[kk][tx * 4 + j];
#pragma unroll
                for (int i = 0; i < 4; i++)
#pragma unroll
                    for (int j = 0; j < 4; j++) acc[i][j] = fmaf(a[i], w[j], acc[i][j]);
            }
            __syncthreads();
        }
    }
#pragma unroll
    for (int i = 0; i < 4; i++) {
        int m = bm + ty * 4 + i;
        if (m >= M) continue;
#pragma unroll
        for (int j = 0; j < 4; j++) {
            int n = bn + tx * 4 + j;
            if (n >= N) continue;
            float v = acc[i][j] + (bias ? bias[n] : 0.0f);
            if (act) v = tanhf(v);
            C[m * ldc + n] = v;
        }
    }
}

// ---------------- max over L for the global feature ----------------
__global__ void maxl_kernel(const float* __restrict__ glob, float* __restrict__ g)
{
    int idx = blockIdx.x * blockDim.x + threadIdx.x;
    if (idx >= BB * HH) return;
    int b = idx / HH, o = idx % HH;
    float m = -INFINITY;
    for (int l = 0; l < LSEQ; l++)
        m = fmaxf(m, glob[(l * BB + b) * HH + o]);
    g[idx] = m;
}

// ---------------- pair kernel: sigmoid(tW . elu(LN(Pst[i]+Pen[j]+Pg)) + tb) * mask ----------------
__global__ __launch_bounds__(256) void pair_kernel(
    const float* __restrict__ Pst, const float* __restrict__ Pen, const float* __restrict__ Pg,
    const float* __restrict__ lng, const float* __restrict__ lnb,
    const float* __restrict__ tW, const float* __restrict__ tb,
    const float* __restrict__ mask, float* __restrict__ out,
    int T, int diag)
{
    __shared__ float sAC[HH], sLG[HH], sLB[HH];
    __shared__ float sTW[12 * HH];
    __shared__ float sTB[12];

    const int i = blockIdx.x, b = blockIdx.y;
    const int tid = threadIdx.x, warp = tid >> 5, lane = tid & 31;

    for (int k = tid; k < HH; k += 256) {
        sAC[k] = Pst[(i * BB + b) * HH + k] + Pg[b * HH + k];
        sLG[k] = lng[k];
        sLB[k] = lnb[k];
    }
    for (int k = tid; k < T * HH; k += 256) sTW[k] = tW[k];
    if (tid < T) sTB[tid] = tb[tid];
    const float mi = mask[i * BB + b];
    __syncthreads();

    for (int j = warp; j < LSEQ; j += 8) {
        float mf = mi * mask[j * BB + b];
        if (diag && j < i) mf = 0.0f;
        int base = ((i * LSEQ + j) * BB + b) * T;
        if (mf == 0.0f) {
            if (lane == 0)
                for (int tg = 0; tg < T; tg++) out[base + tg] = 0.0f;
            continue;
        }
        const float* pen = &Pen[(j * BB + b) * HH];
        float sv[10];
        float sum = 0.f, ss = 0.f;
#pragma unroll
        for (int t = 0; t < 10; t++) {
            int k = lane + t * 32;
            float s = 0.f;
            if (k < HH) s = sAC[k] + __ldg(&pen[k]);
            sv[t] = s;
            sum += s;
            ss = fmaf(s, s, ss);
        }
        sum = wsum(sum);
        ss  = wsum(ss);
        float mu   = sum * (1.0f / HH);
        float var  = ss * (1.0f / HH) - mu * mu;
        float rstd = rsqrtf(var + 1e-5f);
#pragma unroll
        for (int t = 0; t < 10; t++) {
            int k = lane + t * 32;
            float x = 0.f;
            if (k < HH) {
                x = (sv[t] - mu) * rstd * sLG[k] + sLB[k];
                x = x > 0.f ? x : expm1f(x);
            }
            sv[t] = x;
        }
        for (int tg = 0; tg < T; tg++) {
            float acc = 0.f;
#pragma unroll
            for (int t = 0; t < 10; t++) {
                int k = lane + t * 32;
                if (k < HH) acc = fmaf(sv[t], sTW[tg * HH + k], acc);
            }
            acc = wsum(acc);
            if (lane == 0)
                out[base + tg] = mf / (1.0f + expf(-(acc + sTB[tg])));
        }
    }
}

// ---------------- launch ----------------
extern "C" void kernel_launch(void* const* d_in, const int* in_sizes, int n_in,
                              void* d_out, int out_size)
{
    (void)in_sizes; (void)n_in; (void)out_size;
    const float* x      = (const float*)d_in[0];
    const float* mask   = (const float*)d_in[1];
    const float* W_ih   = (const float*)d_in[2];
    const float* b_ih   = (const float*)d_in[3];
    const float* W_hh   = (const float*)d_in[4];
    const float* b_hh   = (const float*)d_in[5];
    const float* W_tr   = (const float*)d_in[6];
    const float* b_tr   = (const float*)d_in[7];
    const float* n_W    = (const float*)d_in[8];
    const float* n_b    = (const float*)d_in[9];
    const float* ner_hW = (const float*)d_in[10];
    const float* ner_hb = (const float*)d_in[11];
    const float* ner_g  = (const float*)d_in[12];
    const float* ner_be = (const float*)d_in[13];
    const float* ner_tW = (const float*)d_in[14];
    const float* ner_tb = (const float*)d_in[15];
    const float* r_W    = (const float*)d_in[16];
    const float* r_b    = (const float*)d_in[17];
    const float* re_hW  = (const float*)d_in[18];
    const float* re_hb  = (const float*)d_in[19];
    const float* re_g   = (const float*)d_in[20];
    const float* re_be  = (const float*)d_in[21];
    const float* re_tW  = (const float*)d_in[22];
    const float* re_tb  = (const float*)d_in[23];
    float* out = (float*)d_out;

    void *rs_p, *pre_p, *hner_p, *hre_p, *hsh_p, *glob_p, *g_p, *pst_p, *pen_p, *pg_p;
    cudaGetSymbolAddress(&rs_p,   g_rs);
    cudaGetSymbolAddress(&pre_p,  d_pre);
    cudaGetSymbolAddress(&hner_p, d_hner);
    cudaGetSymbolAddress(&hre_p,  d_hre);
    cudaGetSymbolAddress(&hsh_p,  d_hsh);
    cudaGetSymbolAddress(&glob_p, d_glob);
    cudaGetSymbolAddress(&g_p,    d_gmax);
    cudaGetSymbolAddress(&pst_p,  d_Pst);
    cudaGetSymbolAddress(&pen_p,  d_Pen);
    cudaGetSymbolAddress(&pg_p,   d_Pg);

    // reset barrier + carries (graph-replay safe)
    cudaMemsetAsync(rs_p, 0, sizeof(RecurState), 0);

    // pre = x @ W_ih^T + b_ih   [512,1500]
    gemm_rt<<<dim3((G5 + TBN - 1) / TBN, (LSEQ * BB + TBM - 1) / TBM), 256>>>(
        x, DD, nullptr, 0, W_ih, DD, 0, 0, b_ih, (float*)pre_p, G5,
        LSEQ * BB, G5, DD, 0, 0);

    // persistent recurrence
    recur_kernel<<<NBLK, 256>>>(W_hh, b_hh, W_tr, b_tr);

    const dim3 gsmall((HH + TBN - 1) / TBN, (LSEQ * BB + TBM - 1) / TBM);  // (5,8)
    const dim3 gtiny((HH + TBN - 1) / TBN, 1);

    // ---- NER unit ----
    gemm_rt<<<gsmall, 256>>>((const float*)hsh_p, HH, (const float*)hner_p, HH,
                             n_W, 2 * HH, 0, HH, n_b, (float*)glob_p, HH,
                             LSEQ * BB, HH, HH, HH, 1);
    maxl_kernel<<<(BB * HH + 255) / 256, 256>>>((const float*)glob_p, (float*)g_p);
    gemm_rt<<<gsmall, 256>>>((const float*)hner_p, HH, nullptr, 0,
                             ner_hW, K3, 0, 0, nullptr, (float*)pst_p, HH,
                             LSEQ * BB, HH, HH, 0, 0);
    gemm_rt<<<gsmall, 256>>>((const float*)hner_p, HH, nullptr, 0,
                             ner_hW, K3, HH, 0, nullptr, (float*)pen_p, HH,
                             LSEQ * BB, HH, HH, 0, 0);
    gemm_rt<<<gtiny, 256>>>((const float*)g_p, HH, nullptr, 0,
                            ner_hW, K3, 2 * HH, 0, ner_hb, (float*)pg_p, HH,
                            BB, HH, HH, 0, 0);
    pair_kernel<<<dim3(LSEQ, BB), 256>>>((const float*)pst_p, (const float*)pen_p,
                                         (const float*)pg_p, ner_g, ner_be,
                                         ner_tW, ner_tb, mask, out, NTAG, 1);

    // ---- RE unit ----
    gemm_rt<<<gsmall, 256>>>((const float*)hsh_p, HH, (const float*)hre_p, HH,
                             r_W, 2 * HH, 0, HH, r_b, (float*)glob_p, HH,
                             LSEQ * BB, HH, HH, HH, 1);
    maxl_kernel<<<(BB * HH + 255) / 256, 256>>>((const float*)glob_p, (float*)g_p);
    gemm_rt<<<gsmall, 256>>>((const float*)hre_p, HH, nullptr, 0,
                             re_hW, K3, 0, 0, nullptr, (float*)pst_p, HH,
                             LSEQ * BB, HH, HH, 0, 0);
    gemm_rt<<<gsmall, 256>>>((const float*)hre_p, HH, nullptr, 0,
                             re_hW, K3, HH, 0, nullptr, (float*)pen_p, HH,
                             LSEQ * BB, HH, HH, 0, 0);
    gemm_rt<<<gtiny, 256>>>((const float*)g_p, HH, nullptr, 0,
                            re_hW, K3, 2 * HH, 0, re_hb, (float*)pg_p, HH,
                            BB, HH, HH, 0, 0);
    pair_kernel<<<dim3(LSEQ, BB), 256>>>((const float*)pst_p, (const float*)pen_p,
                                         (const float*)pg_p, re_g, re_be,
                                         re_tW, re_tb, mask,
                                         out + LSEQ * LSEQ * BB * NTAG, NREL, 0);
}

// round 16
// speedup vs baseline: 1.3112x; 1.3112x over previous
#include <cuda_runtime.h>
#include <math.h>

#define LSEQ 128
#define BB   4
#define DD   768
#define HH   300
#define G5   1500
#define K3   900
#define NTAG 7
#define NREL 12
#define NBLK 64
#define GPC  24   // W_hh gates per CTA  (64*24 = 1536 >= 1500)
#define OPC  5    // W_tr outputs per CTA (64*5 = 320 >= 300)

// ---------------- persistent recurrence state ----------------
struct RecurState {
    unsigned bar;
    unsigned pad[31];
    float h[BB * HH];
    float c[2][BB * HH];
    float gates[BB * G5];
};
__device__ RecurState g_rs;

// ---------------- scratch (device globals; no allocs) ----------------
__device__ float d_pre [LSEQ * BB * G5];
__device__ float d_hner[LSEQ * BB * HH];
__device__ float d_hre [LSEQ * BB * HH];
__device__ float d_hsh [LSEQ * BB * HH];
__device__ float d_glob[LSEQ * BB * HH];
__device__ float d_gmax[BB * HH];
__device__ float d_Pst [LSEQ * BB * HH];
__device__ float d_Pen [LSEQ * BB * HH];
__device__ float d_Pg  [BB * HH];

// ---------------- warp helpers ----------------
__device__ __forceinline__ float wsum(float v) {
#pragma unroll
    for (int o = 16; o; o >>= 1) v += __shfl_xor_sync(0xffffffffu, v, o);
    return v;
}
__device__ __forceinline__ float wmax(float v) {
#pragma unroll
    for (int o = 16; o; o >>= 1) v = fmaxf(v, __shfl_xor_sync(0xffffffffu, v, o));
    return v;
}

// software grid barrier (all NBLK CTAs co-resident; counter memset to 0 per launch)
__device__ __forceinline__ void gbar(unsigned target) {
    __syncthreads();
    if (threadIdx.x == 0) {
        __threadfence();
        atomicAdd(&g_rs.bar, 1u);
        unsigned v;
        do {
            asm volatile("ld.acquire.gpu.global.b32 %0, [%1];"
                         : "=r"(v) : "l"(&g_rs.bar) : "memory");
        } while (v < target);
    }
    __syncthreads();
}

// ---------------- persistent recurrence kernel (weights cached in smem) ----------------
// dynamic smem layout (floats):
//   sWh   [GPC*HH]   = 7200
//   sWt   [OPC*K3]   = 4500
//   sh    [BB*HH]    = 1200
//   sscan [16*HH]    = 4800
//   scat  [BB*K3]    = 3600
#define RECUR_SMEM ((GPC*HH + OPC*K3 + BB*HH + 16*HH + BB*K3) * 4)

__global__ __launch_bounds__(256) void recur_kernel(
    const float* __restrict__ W_hh, const float* __restrict__ b_hh,
    const float* __restrict__ W_tr, const float* __restrict__ b_tr)
{
    extern __shared__ float smem[];
    float* sWh   = smem;
    float* sWt   = sWh + GPC * HH;
    float* sh    = sWt + OPC * K3;
    float* sscan = sh + BB * HH;
    float* scat  = sscan + 16 * HH;

    const int tid  = threadIdx.x;
    const int bid  = blockIdx.x;
    const int warp = tid >> 5;
    const int lane = tid & 31;

    // ---- preload this CTA's weight slices ----
    const int gbase = bid * GPC;
    for (int i = tid; i < GPC * HH; i += 256) {
        int g = gbase + i / HH;
        sWh[i] = (g < G5) ? W_hh[(size_t)g * HH + (i % HH)] : 0.0f;
    }
    const int obase = bid * OPC;
    for (int i = tid; i < OPC * K3; i += 256) {
        int o = obase + i / K3;
        sWt[i] = (o < HH) ? W_tr[(size_t)o * K3 + (i % K3)] : 0.0f;
    }
    float bh[3];
#pragma unroll
    for (int gi = 0; gi < 3; gi++) {
        int g = gbase + warp * 3 + gi;
        bh[gi] = (g < G5) ? b_hh[g] : 0.0f;
    }
    float bt = 0.0f;
    if (warp < OPC) {
        int o = obase + warp;
        if (o < HH) bt = b_tr[o];
    }

    unsigned target = 0;

    for (int l = 0; l < LSEQ; l++) {
        // ---- gather h into smem ----
        for (int i = tid; i < BB * HH; i += 256) sh[i] = __ldcg(&g_rs.h[i]);

        // prefetch pre[l] for this warp's 12 (gate,batch) outputs (lane gi*4+b)
        float prefv = 0.0f;
        if (lane < 12) {
            int gg = gbase + warp * 3 + (lane >> 2);
            if (gg < G5) prefv = __ldg(&d_pre[(l * BB + (lane & 3)) * G5 + gg]);
        }
        __syncthreads();

        // ---- Phase A: gates = pre + h @ W_hh^T + b_hh (smem weights) ----
        {
            float acc[3][4] = {};
            const float* w0 = &sWh[(warp * 3 + 0) * HH];
            const float* w1 = &sWh[(warp * 3 + 1) * HH];
            const float* w2 = &sWh[(warp * 3 + 2) * HH];
            for (int k = lane; k < HH; k += 32) {
                float h0 = sh[k], h1 = sh[HH + k], h2 = sh[2 * HH + k], h3 = sh[3 * HH + k];
                float a = w0[k], b = w1[k], c = w2[k];
                acc[0][0] = fmaf(a, h0, acc[0][0]); acc[0][1] = fmaf(a, h1, acc[0][1]);
                acc[0][2] = fmaf(a, h2, acc[0][2]); acc[0][3] = fmaf(a, h3, acc[0][3]);
                acc[1][0] = fmaf(b, h0, acc[1][0]); acc[1][1] = fmaf(b, h1, acc[1][1]);
                acc[1][2] = fmaf(b, h2, acc[1][2]); acc[1][3] = fmaf(b, h3, acc[1][3]);
                acc[2][0] = fmaf(c, h0, acc[2][0]); acc[2][1] = fmaf(c, h1, acc[2][1]);
                acc[2][2] = fmaf(c, h2, acc[2][2]); acc[2][3] = fmaf(c, h3, acc[2][3]);
            }
#pragma unroll
            for (int gi = 0; gi < 3; gi++) {
                int g = gbase + warp * 3 + gi;
                float s0 = wsum(acc[gi][0]);
                float s1 = wsum(acc[gi][1]);
                float s2 = wsum(acc[gi][2]);
                float s3 = wsum(acc[gi][3]);
                float p0 = __shfl_sync(0xffffffffu, prefv, gi * 4 + 0);
                float p1 = __shfl_sync(0xffffffffu, prefv, gi * 4 + 1);
                float p2 = __shfl_sync(0xffffffffu, prefv, gi * 4 + 2);
                float p3 = __shfl_sync(0xffffffffu, prefv, gi * 4 + 3);
                if (lane == 0 && g < G5) {
                    __stcg(&g_rs.gates[0 * G5 + g], s0 + bh[gi] + p0);
                    __stcg(&g_rs.gates[1 * G5 + g], s1 + bh[gi] + p1);
                    __stcg(&g_rs.gates[2 * G5 + g], s2 + bh[gi] + p2);
                    __stcg(&g_rs.gates[3 * G5 + g], s3 + bh[gi] + p3);
                }
            }
        }
        target += NBLK; gbar(target);

        // ---- Phase C1: cummax scans (redundant per CTA; 2 per warp) ----
        for (int sc = warp; sc < 16; sc += 8) {
            int b  = sc >> 2;
            int ch = (sc & 3) + 1;
            const float* row = &g_rs.gates[b * G5 + ch * HH];
            float v[10];
            float mx = -INFINITY;
            if (lane < 30) {
#pragma unroll
                for (int t = 0; t < 10; t++) { v[t] = __ldcg(&row[lane * 10 + t]); mx = fmaxf(mx, v[t]); }
            }
            mx = wmax(mx);
            float loc = 0.f;
            if (lane < 30) {
#pragma unroll
                for (int t = 0; t < 10; t++) { float e = __expf(v[t] - mx); loc += e; v[t] = loc; }
            }
            float run = loc;
#pragma unroll
            for (int o = 1; o < 32; o <<= 1) {
                float x = __shfl_up_sync(0xffffffffu, run, o);
                if (lane >= o) run += x;
            }
            float total = __shfl_sync(0xffffffffu, run, 31);
            float off = run - loc;
            float inv = 1.0f / total;
            bool isEg = ((sc & 3) == 0) || ((sc & 3) == 2);
            if (lane < 30) {
#pragma unroll
                for (int t = 0; t < 10; t++) {
                    float cm = (off + v[t]) * inv;
                    sscan[sc * HH + lane * 10 + t] = isEg ? (1.0f - cm) : cm;
                }
            }
        }
        __syncthreads();

        // ---- Phase C2: combine (elementwise; output writes spread over 12 CTAs) ----
        const int rd = l & 1, wr = (l & 1) ^ 1;
        for (int idx = tid; idx < BB * HH; idx += 256) {
            int b = idx / HH, hh = idx - b * HH;
            float c   = tanhf(__ldcg(&g_rs.gates[b * G5 + hh]));
            float cin = __ldcg(&g_rs.c[rd][idx]);
            float egi = sscan[(b * 4 + 0) * HH + hh];
            float rgi = sscan[(b * 4 + 1) * HH + hh];
            float egc = sscan[(b * 4 + 2) * HH + hh];
            float rgc = sscan[(b * 4 + 3) * HH + hh];
            float ovc = rgc * egc, upc = rgc - ovc, dnc = egc - ovc;
            float ovi = rgi * egi, upi = rgi - ovi, dni = egi - ovi;
            float share = ovi * cin + ovc * c;
            float cre   = upi * cin + upc * c + share;
            float cner  = dni * cin + dnc * c + share;
            scat[b * K3 + hh]          = cre;
            scat[b * K3 + HH + hh]     = cner;
            scat[b * K3 + 2 * HH + hh] = share;
            if (bid < 12 && (bid & 3) == b) {
                int arr = bid >> 2;   // 0 -> h_re, 1 -> h_ner, 2 -> h_share
                float val = (arr == 0) ? cre : (arr == 1) ? cner : share;
                float* dst = (arr == 0) ? d_hre : (arr == 1) ? d_hner : d_hsh;
                dst[(l * BB + b) * HH + hh] = tanhf(val);
            }
        }
        __syncthreads();

        // ---- Phase C3: c_out = cat @ W_tr^T + b_tr ; h = tanh(c_out) (smem weights) ----
        if (warp < OPC) {
            int o = obase + warp;
            if (o < HH) {
                float a0 = 0.f, a1 = 0.f, a2 = 0.f, a3 = 0.f;
                const float* wrow = &sWt[warp * K3];
                for (int k = lane; k < K3; k += 32) {
                    float w = wrow[k];
                    a0 = fmaf(w, scat[k], a0);
                    a1 = fmaf(w, scat[K3 + k], a1);
                    a2 = fmaf(w, scat[2 * K3 + k], a2);
                    a3 = fmaf(w, scat[3 * K3 + k], a3);
                }
                a0 = wsum(a0); a1 = wsum(a1); a2 = wsum(a2); a3 = wsum(a3);
                if (lane < 4) {
                    float co = a0;
                    if (lane == 1) co = a1;
                    if (lane == 2) co = a2;
                    if (lane == 3) co = a3;
                    co += bt;
                    __stcg(&g_rs.c[wr][lane * HH + o], co);
                    __stcg(&g_rs.h[lane * HH + o], tanhf(co));
                }
            }
        }
        target += NBLK; gbar(target);
    }
}

// ---------------- generic tiled GEMM ----------------
#define TBM 64
#define TBN 64
#define TBK 16
__global__ __launch_bounds__(256) void gemm_rt(
    const float* __restrict__ A1, int lda1,
    const float* __restrict__ A2, int lda2,
    const float* __restrict__ W, int ldw, int kw1, int kw2,
    const float* __restrict__ bias,
    float* __restrict__ C, int ldc,
    int M, int N, int K1, int K2, int act)
{
    __shared__ float sA[TBK][TBM + 1];
    __shared__ float sW[TBK][TBN + 1];
    const int tid = threadIdx.x;
    const int tx = tid & 15, ty = tid >> 4;
    const int bn = blockIdx.x * TBN, bm = blockIdx.y * TBM;
    float acc[4][4] = {};

    for (int pass = 0; pass < 2; pass++) {
        const float* A = pass ? A2 : A1;
        const int K   = pass ? K2 : K1;
        const int lda = pass ? lda2 : lda1;
        const int kw  = pass ? kw2 : kw1;
        if (A == nullptr || K <= 0) continue;
        for (int k0 = 0; k0 < K; k0 += TBK) {
            for (int i = tid; i < TBM * TBK; i += 256) {
                int r = i >> 4, kk = i & 15;
                int gm = bm + r, gk = k0 + kk;
                sA[kk][r] = (gm < M && gk < K) ? A[gm * lda + gk] : 0.0f;
            }
            for (int i = tid; i < TBN * TBK; i += 256) {
                int r = i >> 4, kk = i & 15;
                int gn = bn + r, gk = k0 + kk;
                sW[kk][r] = (gn < N && gk < K) ? W[gn * ldw + kw + gk] : 0.0f;
            }
            __syncthreads();
#pragma unroll
            for (int kk = 0; kk < TBK; kk++) {
                float a[4], w[4];
#pragma unroll
                for (int i = 0; i < 4; i++) a[i] = sA[kk][ty * 4 + i];
#pragma unroll
                for (int j = 0; j < 4; j++) w[j] = sW[kk][tx * 4 + j];
#pragma unroll
                for (int i = 0; i < 4; i++)
#pragma unroll
                    for (int j = 0; j < 4; j++) acc[i][j] = fmaf(a[i], w[j], acc[i][j]);
            }
            __syncthreads();
        }
    }
#pragma unroll
    for (int i = 0; i < 4; i++) {
        int m = bm + ty * 4 + i;
        if (m >= M) continue;
#pragma unroll
        for (int j = 0; j < 4; j++) {
            int n = bn + tx * 4 + j;
            if (n >= N) continue;
            float v = acc[i][j] + (bias ? bias[n] : 0.0f);
            if (act) v = tanhf(v);
            C[m * ldc + n] = v;
        }
    }
}

// ---------------- max over L ----------------
__global__ void maxl_kernel(const float* __restrict__ glob, float* __restrict__ g)
{
    int idx = blockIdx.x * blockDim.x + threadIdx.x;
    if (idx >= BB * HH) return;
    int b = idx / HH, o = idx % HH;
    float m = -INFINITY;
#pragma unroll 8
    for (int l = 0; l < LSEQ; l++)
        m = fmaxf(m, glob[(l * BB + b) * HH + o]);
    g[idx] = m;
}

// ---------------- pair kernel ----------------
__global__ __launch_bounds__(256) void pair_kernel(
    const float* __restrict__ Pst, const float* __restrict__ Pen, const float* __restrict__ Pg,
    const float* __restrict__ lng, const float* __restrict__ lnb,
    const float* __restrict__ tW, const float* __restrict__ tb,
    const float* __restrict__ mask, float* __restrict__ out,
    int T, int diag)
{
    __shared__ float sAC[HH], sLG[HH], sLB[HH];
    __shared__ float sTW[12 * HH];
    __shared__ float sTB[12];

    const int i = blockIdx.x, b = blockIdx.y;
    const int tid = threadIdx.x, warp = tid >> 5, lane = tid & 31;

    for (int k = tid; k < HH; k += 256) {
        sAC[k] = Pst[(i * BB + b) * HH + k] + Pg[b * HH + k];
        sLG[k] = lng[k];
        sLB[k] = lnb[k];
    }
    for (int k = tid; k < T * HH; k += 256) sTW[k] = tW[k];
    if (tid < T) sTB[tid] = tb[tid];
    const float mi = mask[i * BB + b];
    __syncthreads();

    for (int j = warp; j < LSEQ; j += 8) {
        float mf = mi * mask[j * BB + b];
        if (diag && j < i) mf = 0.0f;
        int base = ((i * LSEQ + j) * BB + b) * T;
        if (mf == 0.0f) {
            if (lane == 0)
                for (int tg = 0; tg < T; tg++) out[base + tg] = 0.0f;
            continue;
        }
        const float* pen = &Pen[(j * BB + b) * HH];
        float sv[10];
        float sum = 0.f, ss = 0.f;
#pragma unroll
        for (int t = 0; t < 10; t++) {
            int k = lane + t * 32;
            float s = 0.f;
            if (k < HH) s = sAC[k] + __ldg(&pen[k]);
            sv[t] = s;
            sum += s;
            ss = fmaf(s, s, ss);
        }
        sum = wsum(sum);
        ss  = wsum(ss);
        float mu   = sum * (1.0f / HH);
        float var  = ss * (1.0f / HH) - mu * mu;
        float rstd = rsqrtf(var + 1e-5f);
#pragma unroll
        for (int t = 0; t < 10; t++) {
            int k = lane + t * 32;
            float x = 0.f;
            if (k < HH) {
                x = (sv[t] - mu) * rstd * sLG[k] + sLB[k];
                x = x > 0.f ? x : (__expf(x) - 1.0f);
            }
            sv[t] = x;
        }
        for (int tg = 0; tg < T; tg++) {
            float acc = 0.f;
#pragma unroll
            for (int t = 0; t < 10; t++) {
                int k = lane + t * 32;
                if (k < HH) acc = fmaf(sv[t], sTW[tg * HH + k], acc);
            }
            acc = wsum(acc);
            if (lane == 0)
                out[base + tg] = mf / (1.0f + __expf(-(acc + sTB[tg])));
        }
    }
}

// ---------------- launch ----------------
extern "C" void kernel_launch(void* const* d_in, const int* in_sizes, int n_in,
                              void* d_out, int out_size)
{
    (void)in_sizes; (void)n_in; (void)out_size;
    const float* x      = (const float*)d_in[0];
    const float* mask   = (const float*)d_in[1];
    const float* W_ih   = (const float*)d_in[2];
    const float* b_ih   = (const float*)d_in[3];
    const float* W_hh   = (const float*)d_in[4];
    const float* b_hh   = (const float*)d_in[5];
    const float* W_tr   = (const float*)d_in[6];
    const float* b_tr   = (const float*)d_in[7];
    const float* n_W    = (const float*)d_in[8];
    const float* n_b    = (const float*)d_in[9];
    const float* ner_hW = (const float*)d_in[10];
    const float* ner_hb = (const float*)d_in[11];
    const float* ner_g  = (const float*)d_in[12];
    const float* ner_be = (const float*)d_in[13];
    const float* ner_tW = (const float*)d_in[14];
    const float* ner_tb = (const float*)d_in[15];
    const float* r_W    = (const float*)d_in[16];
    const float* r_b    = (const float*)d_in[17];
    const float* re_hW  = (const float*)d_in[18];
    const float* re_hb  = (const float*)d_in[19];
    const float* re_g   = (const float*)d_in[20];
    const float* re_be  = (const float*)d_in[21];
    const float* re_tW  = (const float*)d_in[22];
    const float* re_tb  = (const float*)d_in[23];
    float* out = (float*)d_out;

    void *rs_p, *pre_p, *hner_p, *hre_p, *hsh_p, *glob_p, *g_p, *pst_p, *pen_p, *pg_p;
    cudaGetSymbolAddress(&rs_p,   g_rs);
    cudaGetSymbolAddress(&pre_p,  d_pre);
    cudaGetSymbolAddress(&hner_p, d_hner);
    cudaGetSymbolAddress(&hre_p,  d_hre);
    cudaGetSymbolAddress(&hsh_p,  d_hsh);
    cudaGetSymbolAddress(&glob_p, d_glob);
    cudaGetSymbolAddress(&g_p,    d_gmax);
    cudaGetSymbolAddress(&pst_p,  d_Pst);
    cudaGetSymbolAddress(&pen_p,  d_Pen);
    cudaGetSymbolAddress(&pg_p,   d_Pg);

    static int attr_set = 0;
    if (!attr_set) {
        cudaFuncSetAttribute(recur_kernel,
                             cudaFuncAttributeMaxDynamicSharedMemorySize, RECUR_SMEM);
        attr_set = 1;
    }

    // reset barrier + carries (graph-replay safe)
    cudaMemsetAsync(rs_p, 0, sizeof(RecurState), 0);

    // pre = x @ W_ih^T + b_ih   [512,1500]
    gemm_rt<<<dim3((G5 + TBN - 1) / TBN, (LSEQ * BB + TBM - 1) / TBM), 256>>>(
        x, DD, nullptr, 0, W_ih, DD, 0, 0, b_ih, (float*)pre_p, G5,
        LSEQ * BB, G5, DD, 0, 0);

    // persistent recurrence
    recur_kernel<<<NBLK, 256, RECUR_SMEM>>>(W_hh, b_hh, W_tr, b_tr);

    const dim3 gsmall((HH + TBN - 1) / TBN, (LSEQ * BB + TBM - 1) / TBM);  // (5,8)
    const dim3 gtiny((HH + TBN - 1) / TBN, 1);

    // ---- NER unit ----
    gemm_rt<<<gsmall, 256>>>((const float*)hsh_p, HH, (const float*)hner_p, HH,
                             n_W, 2 * HH, 0, HH, n_b, (float*)glob_p, HH,
                             LSEQ * BB, HH, HH, HH, 1);
    maxl_kernel<<<(BB * HH + 255) / 256, 256>>>((const float*)glob_p, (float*)g_p);
    gemm_rt<<<gsmall, 256>>>((const float*)hner_p, HH, nullptr, 0,
                             ner_hW, K3, 0, 0, nullptr, (float*)pst_p, HH,
                             LSEQ * BB, HH, HH, 0, 0);
    gemm_rt<<<gsmall, 256>>>((const float*)hner_p, HH, nullptr, 0,
                             ner_hW, K3, HH, 0, nullptr, (float*)pen_p, HH,
                             LSEQ * BB, HH, HH, 0, 0);
    gemm_rt<<<gtiny, 256>>>((const float*)g_p, HH, nullptr, 0,
                            ner_hW, K3, 2 * HH, 0, ner_hb, (float*)pg_p, HH,
                            BB, HH, HH, 0, 0);
    pair_kernel<<<dim3(LSEQ, BB), 256>>>((const float*)pst_p, (const float*)pen_p,
                                         (const float*)pg_p, ner_g, ner_be,
                                         ner_tW, ner_tb, mask, out, NTAG, 1);

    // ---- RE unit ----
    gemm_rt<<<gsmall, 256>>>((const float*)hsh_p, HH, (const float*)hre_p, HH,
                             r_W, 2 * HH, 0, HH, r_b, (float*)glob_p, HH,
                             LSEQ * BB, HH, HH, HH, 1);
    maxl_kernel<<<(BB * HH + 255) / 256, 256>>>((const float*)glob_p, (float*)g_p);
    gemm_rt<<<gsmall, 256>>>((const float*)hre_p, HH, nullptr, 0,
                             re_hW, K3, 0, 0, nullptr, (float*)pst_p, HH,
                             LSEQ * BB, HH, HH, 0, 0);
    gemm_rt<<<gsmall, 256>>>((const float*)hre_p, HH, nullptr, 0,
                             re_hW, K3, HH, 0, nullptr, (float*)pen_p, HH,
                             LSEQ * BB, HH, HH, 0, 0);
    gemm_rt<<<gtiny, 256>>>((const float*)g_p, HH, nullptr, 0,
                            re_hW, K3, 2 * HH, 0, re_hb, (float*)pg_p, HH,
                            BB, HH, HH, 0, 0);
    pair_kernel<<<dim3(LSEQ, BB), 256>>>((const float*)pst_p, (const float*)pen_p,
                                         (const float*)pg_p, re_g, re_be,
                                         re_tW, re_tb, mask,
                                         out + LSEQ * LSEQ * BB * NTAG, NREL, 0);
}

// round 17
// speedup vs baseline: 1.3977x; 1.0659x over previous
#include <cuda_runtime.h>
#include <math.h>

#define LSEQ 128
#define BB   4
#define DD   768
#define HH   300
#define G5   1500
#define K3   900
#define NTAG 7
#define NREL 12
#define NBLK 64
#define GPC  24
#define OPC  5

struct RecurState {
    unsigned bar;
    unsigned pad[31];
    float h[BB * HH];
    float c[2][BB * HH];
    float gates[BB * G5];
};
__device__ RecurState g_rs;

__device__ float d_pre [LSEQ * BB * G5];
__device__ float d_hner[LSEQ * BB * HH];
__device__ float d_hre [LSEQ * BB * HH];
__device__ float d_hsh [LSEQ * BB * HH];
__device__ float d_glob[LSEQ * BB * HH];
__device__ float d_gmax[BB * HH];
__device__ float d_Pst [LSEQ * BB * HH];
__device__ float d_Pen [LSEQ * BB * HH];
__device__ float d_Pg  [BB * HH];
// RE-unit private scratch (parallel stream)
__device__ float d_glob2[LSEQ * BB * HH];
__device__ float d_gmax2[BB * HH];
__device__ float d_Pst2 [LSEQ * BB * HH];
__device__ float d_Pen2 [LSEQ * BB * HH];
__device__ float d_Pg2  [BB * HH];

__device__ __forceinline__ float wsum(float v) {
#pragma unroll
    for (int o = 16; o; o >>= 1) v += __shfl_xor_sync(0xffffffffu, v, o);
    return v;
}
__device__ __forceinline__ float wmax(float v) {
#pragma unroll
    for (int o = 16; o; o >>= 1) v = fmaxf(v, __shfl_xor_sync(0xffffffffu, v, o));
    return v;
}
__device__ __forceinline__ float ftanh(float x) {
    float e = __expf(2.0f * fabsf(x));
    float t = 1.0f - 2.0f / (e + 1.0f);
    return copysignf(t, x);
}

// fast grid barrier: CG-style release-red + acquire-poll (no membar.gl)
__device__ __forceinline__ void gbar(unsigned target) {
    __syncthreads();
    if (threadIdx.x == 0) {
        asm volatile("red.release.gpu.global.add.u32 [%0], %1;"
                     :: "l"(&g_rs.bar), "r"(1u) : "memory");
        unsigned v;
        do {
            asm volatile("ld.acquire.gpu.global.b32 %0, [%1];"
                         : "=r"(v) : "l"(&g_rs.bar) : "memory");
        } while (v < target);
    }
    __syncthreads();
}

#define RECUR_SMEM ((GPC*HH + OPC*K3 + BB*HH + 16*HH + BB*K3) * 4)

__global__ __launch_bounds__(256) void recur_kernel(
    const float* __restrict__ W_hh, const float* __restrict__ b_hh,
    const float* __restrict__ W_tr, const float* __restrict__ b_tr)
{
    extern __shared__ float smem[];
    float* sWh   = smem;
    float* sWt   = sWh + GPC * HH;
    float* sh    = sWt + OPC * K3;
    float* sscan = sh + BB * HH;
    float* scat  = sscan + 16 * HH;

    const int tid  = threadIdx.x;
    const int bid  = blockIdx.x;
    const int warp = tid >> 5;
    const int lane = tid & 31;

    const int gbase = bid * GPC;
    for (int i = tid; i < GPC * HH; i += 256) {
        int g = gbase + i / HH;
        sWh[i] = (g < G5) ? W_hh[(size_t)g * HH + (i % HH)] : 0.0f;
    }
    const int obase = bid * OPC;
    for (int i = tid; i < OPC * K3; i += 256) {
        int o = obase + i / K3;
        sWt[i] = (o < HH) ? W_tr[(size_t)o * K3 + (i % K3)] : 0.0f;
    }
    float bh[3];
#pragma unroll
    for (int gi = 0; gi < 3; gi++) {
        int g = gbase + warp * 3 + gi;
        bh[gi] = (g < G5) ? b_hh[g] : 0.0f;
    }
    float bt = 0.0f;
    if (warp < OPC) {
        int o = obase + warp;
        if (o < HH) bt = b_tr[o];
    }

    unsigned target = 0;

    for (int l = 0; l < LSEQ; l++) {
        for (int i = tid; i < BB * HH; i += 256) sh[i] = __ldcg(&g_rs.h[i]);

        float prefv = 0.0f;
        if (lane < 12) {
            int gg = gbase + warp * 3 + (lane >> 2);
            if (gg < G5) prefv = __ldg(&d_pre[(l * BB + (lane & 3)) * G5 + gg]);
        }
        __syncthreads();

        // Phase A
        {
            float acc[3][4] = {};
            const float* w0 = &sWh[(warp * 3 + 0) * HH];
            const float* w1 = &sWh[(warp * 3 + 1) * HH];
            const float* w2 = &sWh[(warp * 3 + 2) * HH];
            for (int k = lane; k < HH; k += 32) {
                float h0 = sh[k], h1 = sh[HH + k], h2 = sh[2 * HH + k], h3 = sh[3 * HH + k];
                float a = w0[k], b = w1[k], c = w2[k];
                acc[0][0] = fmaf(a, h0, acc[0][0]); acc[0][1] = fmaf(a, h1, acc[0][1]);
                acc[0][2] = fmaf(a, h2, acc[0][2]); acc[0][3] = fmaf(a, h3, acc[0][3]);
                acc[1][0] = fmaf(b, h0, acc[1][0]); acc[1][1] = fmaf(b, h1, acc[1][1]);
                acc[1][2] = fmaf(b, h2, acc[1][2]); acc[1][3] = fmaf(b, h3, acc[1][3]);
                acc[2][0] = fmaf(c, h0, acc[2][0]); acc[2][1] = fmaf(c, h1, acc[2][1]);
                acc[2][2] = fmaf(c, h2, acc[2][2]); acc[2][3] = fmaf(c, h3, acc[2][3]);
            }
#pragma unroll
            for (int gi = 0; gi < 3; gi++) {
                int g = gbase + warp * 3 + gi;
                float s0 = wsum(acc[gi][0]);
                float s1 = wsum(acc[gi][1]);
                float s2 = wsum(acc[gi][2]);
                float s3 = wsum(acc[gi][3]);
                float p0 = __shfl_sync(0xffffffffu, prefv, gi * 4 + 0);
                float p1 = __shfl_sync(0xffffffffu, prefv, gi * 4 + 1);
                float p2 = __shfl_sync(0xffffffffu, prefv, gi * 4 + 2);
                float p3 = __shfl_sync(0xffffffffu, prefv, gi * 4 + 3);
                if (lane == 0 && g < G5) {
                    __stcg(&g_rs.gates[0 * G5 + g], s0 + bh[gi] + p0);
                    __stcg(&g_rs.gates[1 * G5 + g], s1 + bh[gi] + p1);
                    __stcg(&g_rs.gates[2 * G5 + g], s2 + bh[gi] + p2);
                    __stcg(&g_rs.gates[3 * G5 + g], s3 + bh[gi] + p3);
                }
            }
        }
        target += NBLK; gbar(target);

        // Phase C1: scans
        for (int sc = warp; sc < 16; sc += 8) {
            int b  = sc >> 2;
            int ch = (sc & 3) + 1;
            const float* row = &g_rs.gates[b * G5 + ch * HH];
            float v[10];
            float mx = -INFINITY;
            if (lane < 30) {
#pragma unroll
                for (int t = 0; t < 10; t++) { v[t] = __ldcg(&row[lane * 10 + t]); mx = fmaxf(mx, v[t]); }
            }
            mx = wmax(mx);
            float loc = 0.f;
            if (lane < 30) {
#pragma unroll
                for (int t = 0; t < 10; t++) { float e = __expf(v[t] - mx); loc += e; v[t] = loc; }
            }
            float run = loc;
#pragma unroll
            for (int o = 1; o < 32; o <<= 1) {
                float xx = __shfl_up_sync(0xffffffffu, run, o);
                if (lane >= o) run += xx;
            }
            float total = __shfl_sync(0xffffffffu, run, 31);
            float off = run - loc;
            float inv = 1.0f / total;
            bool isEg = ((sc & 3) == 0) || ((sc & 3) == 2);
            if (lane < 30) {
#pragma unroll
                for (int t = 0; t < 10; t++) {
                    float cm = (off + v[t]) * inv;
                    sscan[sc * HH + lane * 10 + t] = isEg ? (1.0f - cm) : cm;
                }
            }
        }
        __syncthreads();

        // Phase C2: combine
        const int rd = l & 1, wr = (l & 1) ^ 1;
        for (int idx = tid; idx < BB * HH; idx += 256) {
            int b = idx / HH, hh = idx - b * HH;
            float c   = ftanh(__ldcg(&g_rs.gates[b * G5 + hh]));
            float cin = __ldcg(&g_rs.c[rd][idx]);
            float egi = sscan[(b * 4 + 0) * HH + hh];
            float rgi = sscan[(b * 4 + 1) * HH + hh];
            float egc = sscan[(b * 4 + 2) * HH + hh];
            float rgc = sscan[(b * 4 + 3) * HH + hh];
            float ovc = rgc * egc, upc = rgc - ovc, dnc = egc - ovc;
            float ovi = rgi * egi, upi = rgi - ovi, dni = egi - ovi;
            float share = ovi * cin + ovc * c;
            float cre   = upi * cin + upc * c + share;
            float cner  = dni * cin + dnc * c + share;
            scat[b * K3 + hh]          = cre;
            scat[b * K3 + HH + hh]     = cner;
            scat[b * K3 + 2 * HH + hh] = share;
            if (bid < 12 && (bid & 3) == b) {
                int arr = bid >> 2;
                float val = (arr == 0) ? cre : (arr == 1) ? cner : share;
                float* dst = (arr == 0) ? d_hre : (arr == 1) ? d_hner : d_hsh;
                dst[(l * BB + b) * HH + hh] = ftanh(val);
            }
        }
        __syncthreads();

        // Phase C3
        if (warp < OPC) {
            int o = obase + warp;
            if (o < HH) {
                float a0 = 0.f, a1 = 0.f, a2 = 0.f, a3 = 0.f;
                const float* wrow = &sWt[warp * K3];
                for (int k = lane; k < K3; k += 32) {
                    float w = wrow[k];
                    a0 = fmaf(w, scat[k], a0);
                    a1 = fmaf(w, scat[K3 + k], a1);
                    a2 = fmaf(w, scat[2 * K3 + k], a2);
                    a3 = fmaf(w, scat[3 * K3 + k], a3);
                }
                a0 = wsum(a0); a1 = wsum(a1); a2 = wsum(a2); a3 = wsum(a3);
                if (lane < 4) {
                    float co = a0;
                    if (lane == 1) co = a1;
                    if (lane == 2) co = a2;
                    if (lane == 3) co = a3;
                    co += bt;
                    __stcg(&g_rs.c[wr][lane * HH + o], co);
                    __stcg(&g_rs.h[lane * HH + o], ftanh(co));
                }
            }
        }
        target += NBLK; gbar(target);
    }
}

#define TBM 64
#define TBN 64
#define TBK 16
__global__ __launch_bounds__(256) void gemm_rt(
    const float* __restrict__ A1, int lda1,
    const float* __restrict__ A2, int lda2,
    const float* __restrict__ W, int ldw, int kw1, int kw2,
    const float* __restrict__ bias,
    float* __restrict__ C, int ldc,
    int M, int N, int K1, int K2, int act)
{
    __shared__ float sA[TBK][TBM + 1];
    __shared__ float sW[TBK][TBN + 1];
    const int tid = threadIdx.x;
    const int tx = tid & 15, ty = tid >> 4;
    const int bn = blockIdx.x * TBN, bm = blockIdx.y * TBM;
    float acc[4][4] = {};

    for (int pass = 0; pass < 2; pass++) {
        const float* A = pass ? A2 : A1;
        const int K   = pass ? K2 : K1;
        const int lda = pass ? lda2 : lda1;
        const int kw  = pass ? kw2 : kw1;
        if (A == nullptr || K <= 0) continue;
        for (int k0 = 0; k0 < K; k0 += TBK) {
            for (int i = tid; i < TBM * TBK; i += 256) {
                int r = i >> 4, kk = i & 15;
                int gm = bm + r, gk = k0 + kk;
                sA[kk][r] = (gm < M && gk < K) ? A[gm * lda + gk] : 0.0f;
            }
            for (int i = tid; i < TBN * TBK; i += 256) {
                int r = i >> 4, kk = i & 15;
                int gn = bn + r, gk = k0 + kk;
                sW[kk][r] = (gn < N && gk < K) ? W[gn * ldw + kw + gk] : 0.0f;
            }
            __syncthreads();
#pragma unroll
            for (int kk = 0; kk < TBK; kk++) {
                float a[4], w[4];
#pragma unroll
                for (int i = 0; i < 4; i++) a[i] = sA[kk][ty * 4 + i];
#pragma unroll
                for (int j = 0; j < 4; j++) w[j] = sW[kk][tx * 4 + j];
#pragma unroll
                for (int i = 0; i < 4; i++)
#pragma unroll
                    for (int j = 0; j < 4; j++) acc[i][j] = fmaf(a[i], w[j], acc[i][j]);
            }
            __syncthreads();
        }
    }
#pragma unroll
    for (int i = 0; i < 4; i++) {
        int m = bm + ty * 4 + i;
        if (m >= M) continue;
#pragma unroll
        for (int j = 0; j < 4; j++) {
            int n = bn + tx * 4 + j;
            if (n >= N) continue;
            float v = acc[i][j] + (bias ? bias[n] : 0.0f);
            if (act) v = ftanh(v);
            C[m * ldc + n] = v;
        }
    }
}

__global__ void maxl_kernel(const float* __restrict__ glob, float* __restrict__ g)
{
    int idx = blockIdx.x * blockDim.x + threadIdx.x;
    if (idx >= BB * HH) return;
    int b = idx / HH, o = idx % HH;
    float m = -INFINITY;
#pragma unroll 8
    for (int l = 0; l < LSEQ; l++)
        m = fmaxf(m, glob[(l * BB + b) * HH + o]);
    g[idx] = m;
}

__global__ __launch_bounds__(256) void pair_kernel(
    const float* __restrict__ Pst, const float* __restrict__ Pen, const float* __restrict__ Pg,
    const float* __restrict__ lng, const float* __restrict__ lnb,
    const float* __restrict__ tW, const float* __restrict__ tb,
    const float* __restrict__ mask, float* __restrict__ out,
    int T, int diag)
{
    __shared__ float sAC[HH], sLG[HH], sLB[HH];
    __shared__ float sTW[12 * HH];
    __shared__ float sTB[12];

    const int i = blockIdx.x, b = blockIdx.y;
    const int tid = threadIdx.x, warp = tid >> 5, lane = tid & 31;

    for (int k = tid; k < HH; k += 256) {
        sAC[k] = Pst[(i * BB + b) * HH + k] + Pg[b * HH + k];
        sLG[k] = lng[k];
        sLB[k] = lnb[k];
    }
    for (int k = tid; k < T * HH; k += 256) sTW[k] = tW[k];
    if (tid < T) sTB[tid] = tb[tid];
    const float mi = mask[i * BB + b];
    __syncthreads();

    for (int j = warp; j < LSEQ; j += 8) {
        float mf = mi * mask[j * BB + b];
        if (diag && j < i) mf = 0.0f;
        int base = ((i * LSEQ + j) * BB + b) * T;
        if (mf == 0.0f) {
            if (lane == 0)
                for (int tg = 0; tg < T; tg++) out[base + tg] = 0.0f;
            continue;
        }
        const float* pen = &Pen[(j * BB + b) * HH];
        float sv[10];
        float sum = 0.f, ss = 0.f;
#pragma unroll
        for (int t = 0; t < 10; t++) {
            int k = lane + t * 32;
            float s = 0.f;
            if (k < HH) s = sAC[k] + __ldg(&pen[k]);
            sv[t] = s;
            sum += s;
            ss = fmaf(s, s, ss);
        }
        sum = wsum(sum);
        ss  = wsum(ss);
        float mu   = sum * (1.0f / HH);
        float var  = ss * (1.0f / HH) - mu * mu;
        float rstd = rsqrtf(var + 1e-5f);
#pragma unroll
        for (int t = 0; t < 10; t++) {
            int k = lane + t * 32;
            float x = 0.f;
            if (k < HH) {
                x = (sv[t] - mu) * rstd * sLG[k] + sLB[k];
                x = x > 0.f ? x : (__expf(x) - 1.0f);
            }
            sv[t] = x;
        }
        for (int tg = 0; tg < T; tg++) {
            float acc = 0.f;
#pragma unroll
            for (int t = 0; t < 10; t++) {
                int k = lane + t * 32;
                if (k < HH) acc = fmaf(sv[t], sTW[tg * HH + k], acc);
            }
            acc = wsum(acc);
            if (lane == 0)
                out[base + tg] = mf / (1.0f + __expf(-(acc + sTB[tg])));
        }
    }
}

extern "C" void kernel_launch(void* const* d_in, const int* in_sizes, int n_in,
                              void* d_out, int out_size)
{
    (void)in_sizes; (void)n_in; (void)out_size;
    const float* x      = (const float*)d_in[0];
    const float* mask   = (const float*)d_in[1];
    const float* W_ih   = (const float*)d_in[2];
    const float* b_ih   = (const float*)d_in[3];
    const float* W_hh   = (const float*)d_in[4];
    const float* b_hh   = (const float*)d_in[5];
    const float* W_tr   = (const float*)d_in[6];
    const float* b_tr   = (const float*)d_in[7];
    const float* n_W    = (const float*)d_in[8];
    const float* n_b    = (const float*)d_in[9];
    const float* ner_hW = (const float*)d_in[10];
    const float* ner_hb = (const float*)d_in[11];
    const float* ner_g  = (const float*)d_in[12];
    const float* ner_be = (const float*)d_in[13];
    const float* ner_tW = (const float*)d_in[14];
    const float* ner_tb = (const float*)d_in[15];
    const float* r_W    = (const float*)d_in[16];
    const float* r_b    = (const float*)d_in[17];
    const float* re_hW  = (const float*)d_in[18];
    const float* re_hb  = (const float*)d_in[19];
    const float* re_gn  = (const float*)d_in[20];
    const float* re_be  = (const float*)d_in[21];
    const float* re_tW  = (const float*)d_in[22];
    const float* re_tb  = (const float*)d_in[23];
    float* out = (float*)d_out;

    void *rs_p, *pre_p, *hner_p, *hre_p, *hsh_p;
    void *glob_p, *g_p, *pst_p, *pen_p, *pg_p;
    void *glob2_p, *g2_p, *pst2_p, *pen2_p, *pg2_p;
    cudaGetSymbolAddress(&rs_p,   g_rs);
    cudaGetSymbolAddress(&pre_p,  d_pre);
    cudaGetSymbolAddress(&hner_p, d_hner);
    cudaGetSymbolAddress(&hre_p,  d_hre);
    cudaGetSymbolAddress(&hsh_p,  d_hsh);
    cudaGetSymbolAddress(&glob_p, d_glob);
    cudaGetSymbolAddress(&g_p,    d_gmax);
    cudaGetSymbolAddress(&pst_p,  d_Pst);
    cudaGetSymbolAddress(&pen_p,  d_Pen);
    cudaGetSymbolAddress(&pg_p,   d_Pg);
    cudaGetSymbolAddress(&glob2_p, d_glob2);
    cudaGetSymbolAddress(&g2_p,    d_gmax2);
    cudaGetSymbolAddress(&pst2_p,  d_Pst2);
    cudaGetSymbolAddress(&pen2_p,  d_Pen2);
    cudaGetSymbolAddress(&pg2_p,   d_Pg2);

    static int init_done = 0;
    static cudaStream_t s2;
    static cudaEvent_t ev_fork, ev_join;
    if (!init_done) {
        cudaFuncSetAttribute(recur_kernel,
                             cudaFuncAttributeMaxDynamicSharedMemorySize, RECUR_SMEM);
        cudaStreamCreateWithFlags(&s2, cudaStreamNonBlocking);
        cudaEventCreateWithFlags(&ev_fork, cudaEventDisableTiming);
        cudaEventCreateWithFlags(&ev_join, cudaEventDisableTiming);
        init_done = 1;
    }

    cudaMemsetAsync(rs_p, 0, sizeof(RecurState), 0);

    gemm_rt<<<dim3((G5 + TBN - 1) / TBN, (LSEQ * BB + TBM - 1) / TBM), 256>>>(
        x, DD, nullptr, 0, W_ih, DD, 0, 0, b_ih, (float*)pre_p, G5,
        LSEQ * BB, G5, DD, 0, 0);

    recur_kernel<<<NBLK, 256, RECUR_SMEM>>>(W_hh, b_hh, W_tr, b_tr);

    const dim3 gsmall((HH + TBN - 1) / TBN, (LSEQ * BB + TBM - 1) / TBM);
    const dim3 gtiny((HH + TBN - 1) / TBN, 1);

    // fork RE unit onto s2
    cudaEventRecord(ev_fork, 0);
    cudaStreamWaitEvent(s2, ev_fork, 0);

    // ---- NER unit (main stream) ----
    gemm_rt<<<gsmall, 256>>>((const float*)hsh_p, HH, (const float*)hner_p, HH,
                             n_W, 2 * HH, 0, HH, n_b, (float*)glob_p, HH,
                             LSEQ * BB, HH, HH, HH, 1);
    maxl_kernel<<<(BB * HH + 255) / 256, 256>>>((const float*)glob_p, (float*)g_p);
    gemm_rt<<<gsmall, 256>>>((const float*)hner_p, HH, nullptr, 0,
                             ner_hW, K3, 0, 0, nullptr, (float*)pst_p, HH,
                             LSEQ * BB, HH, HH, 0, 0);
    gemm_rt<<<gsmall, 256>>>((const float*)hner_p, HH, nullptr, 0,
                             ner_hW, K3, HH, 0, nullptr, (float*)pen_p, HH,
                             LSEQ * BB, HH, HH, 0, 0);
    gemm_rt<<<gtiny, 256>>>((const float*)g_p, HH, nullptr, 0,
                            ner_hW, K3, 2 * HH, 0, ner_hb, (float*)pg_p, HH,
                            BB, HH, HH, 0, 0);
    pair_kernel<<<dim3(LSEQ, BB), 256>>>((const float*)pst_p, (const float*)pen_p,
                                         (const float*)pg_p, ner_g, ner_be,
                                         ner_tW, ner_tb, mask, out, NTAG, 1);

    // ---- RE unit (stream s2, private scratch) ----
    gemm_rt<<<gsmall, 256, 0, s2>>>((const float*)hsh_p, HH, (const float*)hre_p, HH,
                                    r_W, 2 * HH, 0, HH, r_b, (float*)glob2_p, HH,
                                    LSEQ * BB, HH, HH, HH, 1);
    maxl_kernel<<<(BB * HH + 255) / 256, 256, 0, s2>>>((const float*)glob2_p, (float*)g2_p);
    gemm_rt<<<gsmall, 256, 0, s2>>>((const float*)hre_p, HH, nullptr, 0,
                                    re_hW, K3, 0, 0, nullptr, (float*)pst2_p, HH,
                                    LSEQ * BB, HH, HH, 0, 0);
    gemm_rt<<<gsmall, 256, 0, s2>>>((const float*)hre_p, HH, nullptr, 0,
                                    re_hW, K3, HH, 0, nullptr, (float*)pen2_p, HH,
                                    LSEQ * BB, HH, HH, 0, 0);
    gemm_rt<<<gtiny, 256, 0, s2>>>((const float*)g2_p, HH, nullptr, 0,
                                   re_hW, K3, 2 * HH, 0, re_hb, (float*)pg2_p, HH,
                                   BB, HH, HH, 0, 0);
    pair_kernel<<<dim3(LSEQ, BB), 256, 0, s2>>>((const float*)pst2_p, (const float*)pen2_p,
                                                (const float*)pg2_p, re_gn, re_be,
                                                re_tW, re_tb, mask,
                                                out + LSEQ * LSEQ * BB * NTAG, NREL, 0);

    // join
    cudaEventRecord(ev_join, s2);
    cudaStreamWaitEvent(0, ev_join, 0);
}